// round 1
// baseline (speedup 1.0000x reference)
#include <cuda_runtime.h>

#define PPN 100
#define THREADS 256

__global__ __launch_bounds__(THREADS) void pfn_kernel(
    const float* __restrict__ px, const float* __restrict__ py,
    const float* __restrict__ pz, const float* __restrict__ pi,
    const int*   __restrict__ nv,
    const float* __restrict__ xs, const float* __restrict__ ys,
    const float* __restrict__ mask,
    const float* __restrict__ W,  const float* __restrict__ gamma,
    const float* __restrict__ beta, const float* __restrict__ bmean,
    const float* __restrict__ bvar,
    float* __restrict__ out)
{
    __shared__ float sx[PPN], sy[PPN], sz[PPN], si[PPN], sxs[PPN], sys[PPN], sm[PPN];
    __shared__ float sW[9][32];      // BN-folded weights, [c][u]
    __shared__ float sb[32];         // BN-folded bias
    __shared__ float ssum[3];
    __shared__ float pmax[32][33];   // [n_group][channel], padded row
    __shared__ float bmax[32];

    const int p   = blockIdx.x;
    const int tid = threadIdx.x;
    const size_t off = (size_t)p * PPN;

    // Fold BN (eval mode) into weights/bias
    if (tid < 32) {
        float s = rsqrtf(bvar[tid] + 1e-3f) * gamma[tid];
        sb[tid] = beta[tid] - bmean[tid] * s;
        #pragma unroll
        for (int c = 0; c < 9; c++) sW[c][tid] = W[tid * 9 + c] * s;
    }

    // Stage per-point data
    for (int n = tid; n < PPN; n += THREADS) {
        sx[n]  = px[off + n];  sy[n]  = py[off + n];  sz[n] = pz[off + n];
        si[n]  = pi[off + n];  sxs[n] = xs[off + n];  sys[n] = ys[off + n];
        sm[n]  = mask[off + n];
    }
    __syncthreads();

    // points_mean: sum over ALL N slots (reference semantics), / num_voxels
    const int wid = tid >> 5, lane = tid & 31;
    if (wid < 3) {
        const float* a = (wid == 0) ? sx : ((wid == 1) ? sy : sz);
        float s = 0.f;
        for (int n = lane; n < PPN; n += 32) s += a[n];
        #pragma unroll
        for (int o = 16; o; o >>= 1) s += __shfl_down_sync(0xffffffffu, s, o);
        if (lane == 0) ssum[wid] = s;
    }
    __syncthreads();

    const float fnv = (float)nv[p];
    const float mx = ssum[0] / fnv, my = ssum[1] / fnv, mz = ssum[2] / fnv;

    const int q  = tid & 7;    // channel quad (4 channels)
    const int ng = tid >> 3;   // n slot within a 32-n group

    // Weight micro-tile into registers: channels [4q, 4q+4)
    float w[9][4], b[4];
    #pragma unroll
    for (int c = 0; c < 9; c++)
        #pragma unroll
        for (int j = 0; j < 4; j++) w[c][j] = sW[c][q * 4 + j];
    #pragma unroll
    for (int j = 0; j < 4; j++) b[j] = sb[q * 4 + j];

    float vmax[4] = {-1e30f, -1e30f, -1e30f, -1e30f};
    float4* out4 = (float4*)(out + off * 64);   // 16 float4 per point (64 ch)

    #pragma unroll
    for (int base = 0; base < PPN; base += 32) {
        const int n = base + ng;
        if (n < PPN) {
            const float m = sm[n];
            float f[9];
            f[0] = sx[n]; f[1] = sy[n]; f[2] = sz[n]; f[3] = si[n];
            f[4] = sx[n] - mx; f[5] = sy[n] - my; f[6] = sz[n] - mz;
            f[7] = sx[n] - sxs[n]; f[8] = sy[n] - sys[n];

            float acc[4] = {0.f, 0.f, 0.f, 0.f};
            #pragma unroll
            for (int c = 0; c < 9; c++)
                #pragma unroll
                for (int j = 0; j < 4; j++) acc[j] = fmaf(f[c], w[c][j], acc[j]);

            float r[4];
            #pragma unroll
            for (int j = 0; j < 4; j++) {
                r[j] = fmaxf(fmaf(m, acc[j], b[j]), 0.f);   // mask factored, BN folded, ReLU
                vmax[j] = fmaxf(vmax[j], r[j]);
            }
            float4 v; v.x = r[0]; v.y = r[1]; v.z = r[2]; v.w = r[3];
            out4[(size_t)n * 16 + q] = v;                   // channels [0,32)
        }
    }

    #pragma unroll
    for (int j = 0; j < 4; j++) pmax[ng][q * 4 + j] = vmax[j];
    __syncthreads();

    if (tid < 32) {
        float v = pmax[0][tid];
        #pragma unroll
        for (int r2 = 1; r2 < 32; r2++) v = fmaxf(v, pmax[r2][tid]);
        bmax[tid] = v;
    }
    __syncthreads();

    float4 bc;
    bc.x = bmax[q * 4 + 0]; bc.y = bmax[q * 4 + 1];
    bc.z = bmax[q * 4 + 2]; bc.w = bmax[q * 4 + 3];
    #pragma unroll
    for (int base = 0; base < PPN; base += 32) {
        const int n = base + ng;
        if (n < PPN) out4[(size_t)n * 16 + 8 + q] = bc;     // channels [32,64) = broadcast max
    }
}

extern "C" void kernel_launch(void* const* d_in, const int* in_sizes, int n_in,
                              void* d_out, int out_size)
{
    const float* px    = (const float*)d_in[0];
    const float* py    = (const float*)d_in[1];
    const float* pz    = (const float*)d_in[2];
    const float* pi    = (const float*)d_in[3];
    const int*   nv    = (const int*  )d_in[4];
    const float* xs    = (const float*)d_in[5];
    const float* ys    = (const float*)d_in[6];
    const float* mask  = (const float*)d_in[7];
    const float* W     = (const float*)d_in[8];
    const float* gamma = (const float*)d_in[9];
    const float* beta  = (const float*)d_in[10];
    const float* bmean = (const float*)d_in[11];
    const float* bvar  = (const float*)d_in[12];

    const int P = in_sizes[4];   // num_voxels has one entry per pillar
    pfn_kernel<<<P, THREADS>>>(px, py, pz, pi, nv, xs, ys, mask,
                               W, gamma, beta, bmean, bvar, (float*)d_out);
}

// round 2
// speedup vs baseline: 1.2860x; 1.2860x over previous
#include <cuda_runtime.h>

#define PPN 100
#define THREADS 256

__global__ __launch_bounds__(THREADS, 4) void pfn_kernel(
    const float* __restrict__ px, const float* __restrict__ py,
    const float* __restrict__ pz, const float* __restrict__ pi,
    const int*   __restrict__ nv,
    const float* __restrict__ xs, const float* __restrict__ ys,
    const float* __restrict__ W,  const float* __restrict__ gamma,
    const float* __restrict__ beta, const float* __restrict__ bmean,
    const float* __restrict__ bvar,
    float* __restrict__ out)
{
    // staged per-point inputs: x,y,z,i,xs,ys  (row = 400B, 16B aligned)
    __shared__ __align__(16) float sdata[6][PPN];
    // folded weights: [0]=wx [1]=wy [2]=wz [3]=wi [4]=wxs [5]=wys [6]=w4 [7]=w5 [8]=w6 [9]=bias
    __shared__ float sW[10][32];
    __shared__ float ssum[3];
    __shared__ float pmax[32][33];
    __shared__ float bmax[32];

    const int p   = blockIdx.x;
    const int tid = threadIdx.x;
    const size_t off = (size_t)p * PPN;

    // ---- fold BN + feature algebra into weights (one warp) ----
    if (tid < 32) {
        const float* Wr = W + tid * 9;
        float w0 = Wr[0], w1 = Wr[1], w2 = Wr[2], w3 = Wr[3];
        float w4 = Wr[4], w5 = Wr[5], w6 = Wr[6], w7 = Wr[7], w8 = Wr[8];
        float s = rsqrtf(bvar[tid] + 1e-3f) * gamma[tid];
        sW[0][tid] = (w0 + w4 + w7) * s;   // x
        sW[1][tid] = (w1 + w5 + w8) * s;   // y
        sW[2][tid] = (w2 + w6) * s;        // z
        sW[3][tid] = w3 * s;               // intensity
        sW[4][tid] = -w7 * s;              // x_sub
        sW[5][tid] = -w8 * s;              // y_sub
        sW[6][tid] = w4 * s;               // for mean-x constant
        sW[7][tid] = w5 * s;               // for mean-y constant
        sW[8][tid] = w6 * s;               // for mean-z constant
        sW[9][tid] = beta[tid] - bmean[tid] * s;
    }

    // ---- stage inputs: 6 arrays x 25 float4 = 150 vector loads ----
    if (tid < 150) {
        const int a = tid / 25, j = tid % 25;
        const float* src = (a == 0) ? px : (a == 1) ? py : (a == 2) ? pz
                         : (a == 3) ? pi : (a == 4) ? xs : ys;
        ((float4*)&sdata[a][0])[j] = ((const float4*)(src + off))[j];
    }
    __syncthreads();

    // ---- points_mean: sum over ALL N slots (reference semantics) ----
    const int wid = tid >> 5, lane = tid & 31;
    if (wid < 3) {
        const float* a = sdata[wid];
        float s = 0.f;
        #pragma unroll
        for (int n = lane; n < PPN; n += 32) s += a[n];
        #pragma unroll
        for (int o = 16; o; o >>= 1) s += __shfl_down_sync(0xffffffffu, s, o);
        if (lane == 0) ssum[wid] = s;
    }
    __syncthreads();

    const int   nvp = nv[p];
    const float fnv = (float)nvp;
    const float mx = ssum[0] / fnv, my = ssum[1] / fnv, mz = ssum[2] / fnv;

    const int q  = tid & 7;    // channel quad
    const int ng = tid >> 3;   // point slot within a 32-point group

    // per-thread weight micro-tile: 6 folded weights + bias + per-pillar K
    float wx[4], wy[4], wz[4], wi[4], wxs[4], wys[4], b[4], K[4];
    #pragma unroll
    for (int j = 0; j < 4; j++) {
        const int u = q * 4 + j;
        wx[j]  = sW[0][u]; wy[j]  = sW[1][u]; wz[j] = sW[2][u];
        wi[j]  = sW[3][u]; wxs[j] = sW[4][u]; wys[j] = sW[5][u];
        b[j]   = sW[9][u];
        K[j]   = -(mx * sW[6][u] + my * sW[7][u] + mz * sW[8][u]);
    }

    float vmax[4] = {-1e30f, -1e30f, -1e30f, -1e30f};
    float4* out4 = (float4*)(out + off * 64);   // 16 float4 per point

    #pragma unroll
    for (int base = 0; base < PPN; base += 32) {
        const int n = base + ng;
        if (n < PPN) {
            const float x  = sdata[0][n], y  = sdata[1][n], z = sdata[2][n];
            const float it = sdata[3][n], xv = sdata[4][n], yv = sdata[5][n];
            const float m  = (n < nvp) ? 1.f : 0.f;

            float r[4];
            #pragma unroll
            for (int j = 0; j < 4; j++) {
                float acc = K[j];
                acc = fmaf(x,  wx[j],  acc);
                acc = fmaf(y,  wy[j],  acc);
                acc = fmaf(z,  wz[j],  acc);
                acc = fmaf(it, wi[j],  acc);
                acc = fmaf(xv, wxs[j], acc);
                acc = fmaf(yv, wys[j], acc);
                r[j] = fmaxf(fmaf(m, acc, b[j]), 0.f);
                vmax[j] = fmaxf(vmax[j], r[j]);
            }
            float4 v; v.x = r[0]; v.y = r[1]; v.z = r[2]; v.w = r[3];
            __stcs(&out4[(size_t)n * 16 + q], v);           // channels [0,32)
        }
    }

    #pragma unroll
    for (int j = 0; j < 4; j++) pmax[ng][q * 4 + j] = vmax[j];
    __syncthreads();

    if (tid < 32) {
        float v = pmax[0][tid];
        #pragma unroll
        for (int r2 = 1; r2 < 32; r2++) v = fmaxf(v, pmax[r2][tid]);
        bmax[tid] = v;
    }
    __syncthreads();

    float4 bc;
    bc.x = bmax[q * 4 + 0]; bc.y = bmax[q * 4 + 1];
    bc.z = bmax[q * 4 + 2]; bc.w = bmax[q * 4 + 3];
    #pragma unroll
    for (int base = 0; base < PPN; base += 32) {
        const int n = base + ng;
        if (n < PPN) __stcs(&out4[(size_t)n * 16 + 8 + q], bc);  // channels [32,64)
    }
}

extern "C" void kernel_launch(void* const* d_in, const int* in_sizes, int n_in,
                              void* d_out, int out_size)
{
    const float* px    = (const float*)d_in[0];
    const float* py    = (const float*)d_in[1];
    const float* pz    = (const float*)d_in[2];
    const float* pi    = (const float*)d_in[3];
    const int*   nv    = (const int*  )d_in[4];
    const float* xs    = (const float*)d_in[5];
    const float* ys    = (const float*)d_in[6];
    // d_in[7] = mask : derivable from num_voxels, not read
    const float* W     = (const float*)d_in[8];
    const float* gamma = (const float*)d_in[9];
    const float* beta  = (const float*)d_in[10];
    const float* bmean = (const float*)d_in[11];
    const float* bvar  = (const float*)d_in[12];

    const int P = in_sizes[4];
    pfn_kernel<<<P, THREADS>>>(px, py, pz, pi, nv, xs, ys,
                               W, gamma, beta, bmean, bvar, (float*)d_out);
}